// round 4
// baseline (speedup 1.0000x reference)
#include <cuda_runtime.h>

// Problem constants
#define B_    32
#define L_    1855
#define K_    7
#define T_    40
#define CIN   8
#define COUT  32
#define TKS   5
#define TOUT  36      // T - TKS + 1
#define HALF  18      // TOUT / 2
#define WLEN  22      // HALF + TKS - 1 (sliding window per half)

typedef unsigned long long u64;

// Packed fp32x2 FMA (Blackwell). d = a*b + c on both 32-bit halves.
__device__ __forceinline__ u64 ffma2(u64 a, u64 b, u64 c) {
    u64 d;
    asm("fma.rn.f32x2 %0, %1, %2, %3;" : "=l"(d) : "l"(a), "l"(b), "l"(c));
    return d;
}
__device__ __forceinline__ u64 pack2(float lo, float hi) {
    u64 d;
    asm("mov.b64 %0, {%1, %2};" : "=l"(d) : "f"(lo), "f"(hi));
    return d;
}
__device__ __forceinline__ void unpack2(u64 v, float& lo, float& hi) {
    asm("mov.b64 {%0, %1}, %2;" : "=f"(lo), "=f"(hi) : "l"(v));
}

// One warp per (b, l). lane = output channel o.
// SMEM holds gathered, masked neighbor features rearranged as float2:
//   xs2[k][i][t'] = ( x[b, j_k, t',    i],
//                     x[b, j_k, t'+18, i] )   for t' in [0, 22)
// so each f32x2 FMA computes outputs for t and t+18 simultaneously.
__global__ void __launch_bounds__(32)
indexed_conv_kernel(const float* __restrict__ x,
                    const int*   __restrict__ nidx,
                    const float* __restrict__ W,
                    const float* __restrict__ bias,
                    float*       __restrict__ out)
{
    __shared__ u64   xs2[K_ * CIN * WLEN];   // 9856 B
    __shared__ int   sj[K_];
    __shared__ float sm[K_];

    const int l    = blockIdx.x;
    const int b    = blockIdx.y;
    const int lane = threadIdx.x;

    if (lane < K_) {
        int j = nidx[l * K_ + lane];
        sj[lane] = (j >= 0) ? j : 0;
        sm[lane] = (j >= 0) ? 1.0f : 0.0f;
    }
    __syncthreads();

    float* xsF = reinterpret_cast<float*>(xs2);

    // Cooperative gather: 7 rows x 40 t x 8 i, read as float4 (2 float4 per t),
    // scatter into the (t, t+18)-interleaved layout with mask applied.
    for (int q = lane; q < K_ * T_ * 2; q += 32) {
        int k  = q / (T_ * 2);
        int r  = q - k * (T_ * 2);
        int t  = r >> 1;
        int i4 = (r & 1) << 2;
        const float4 v4 = *reinterpret_cast<const float4*>(
            x + (((size_t)b * L_ + sj[k]) * T_ + t) * CIN + i4);
        const float m = sm[k];
        float vals[4] = {v4.x * m, v4.y * m, v4.z * m, v4.w * m};
        #pragma unroll
        for (int c = 0; c < 4; c++) {
            int i    = i4 + c;
            int base = (k * CIN + i) * WLEN;
            if (t < WLEN)  xsF[(base + t) * 2]              = vals[c];
            if (t >= HALF) xsF[(base + (t - HALF)) * 2 + 1] = vals[c];
        }
    }
    __syncthreads();

    const float bv = bias[lane];
    u64 acc[HALF];
    const u64 binit = pack2(bv, bv);
    #pragma unroll
    for (int t = 0; t < HALF; t++) acc[t] = binit;

    // Main loop: for each (k, i): 22 broadcast LDS.64 + 5 W LDGs (L1-hot,
    // 128B coalesced) + 90 f32x2 FMAs. All lanes read identical x addresses
    // (broadcast, conflict-free); W reads are lane-consecutive.
    for (int k = 0; k < K_; k++) {
        #pragma unroll
        for (int i = 0; i < CIN; i++) {
            const u64* xp = xs2 + (k * CIN + i) * WLEN;
            u64 xr[WLEN];
            #pragma unroll
            for (int t = 0; t < WLEN; t++) xr[t] = xp[t];
            #pragma unroll
            for (int tau = 0; tau < TKS; tau++) {
                float wv = W[((k * TKS + tau) * CIN + i) * COUT + lane];
                u64 w2 = pack2(wv, wv);
                #pragma unroll
                for (int t = 0; t < HALF; t++)
                    acc[t] = ffma2(xr[t + tau], w2, acc[t]);
            }
        }
    }

    // Write out: acc[t] = (out[t], out[t+18]); lane-coalesced 128B stores per t.
    float* op = out + (((size_t)b * L_ + l) * TOUT) * COUT + lane;
    #pragma unroll
    for (int t = 0; t < HALF; t++) {
        float lo, hi;
        unpack2(acc[t], lo, hi);
        op[t * COUT]          = lo;
        op[(t + HALF) * COUT] = hi;
    }
}

extern "C" void kernel_launch(void* const* d_in, const int* in_sizes, int n_in,
                              void* d_out, int out_size)
{
    const float* x    = (const float*)d_in[0];
    const int*   nidx = (const int*)  d_in[1];
    const float* W    = (const float*)d_in[2];
    const float* bias = (const float*)d_in[3];
    float*       out  = (float*)d_out;

    dim3 grid(L_, B_);
    indexed_conv_kernel<<<grid, 32>>>(x, nidx, W, bias, out);
}

// round 7
// speedup vs baseline: 1.8487x; 1.8487x over previous
#include <cuda_runtime.h>
#include <cuda_bf16.h>
#include <cstdint>

// Problem constants
#define B_    32
#define L_    1855
#define K_    7
#define T_    40
#define CIN   8
#define COUT  32
#define TKS   5
#define TOUT  36

// Tiling
#define NSLOT   4                 // b's per CTA (one warp each)
#define XROWS   48                // 40 data rows + pad (sliding window reach 43)
#define XSTRIDE 144               // bytes per row: 64 bf16 = 128 B data + 16 B pad
#define XSLOT   (XROWS * XSTRIDE) // 6912 B per (slot, split)
#define OFF_XLO (NSLOT * XSLOT)   // 27648
#define X_TOTAL (2 * NSLOT * XSLOT) // 55296
#define SMEM_DYN (X_TOTAL)

// W fragments: [mt(2)][tau(5)][kc(4)][ws(2)] x 32 lanes, uint4 each = 40 KB
#define NFRAG (2 * 5 * 4 * 2 * 32)
__device__ uint4 g_wfrag[NFRAG];

// ---------------------------------------------------------------------------
// Pre-kernel: build m16n8k16 A-fragments of W (bf16 hi / lo splits), per lane.
// A is row-major M=o(16) x K=kk(16). Fragment reg layout (PTX m16n8k16):
//   reg0: (r,    k0..k0+1)  reg1: (r+8, k0..k0+1)
//   reg2: (r,    k0+8..9)   reg3: (r+8, k0+8..9)     r = lane>>2, k0 = (lane&3)*2
// ---------------------------------------------------------------------------
__global__ void wfrag_kernel(const float* __restrict__ W)
{
    int idx = blockIdx.x * blockDim.x + threadIdx.x;
    if (idx >= NFRAG) return;
    int lane = idx & 31, rest = idx >> 5;       // rest = ((mt*5+tau)*4+kc)*2+ws
    int ws  = rest & 1;
    int kc  = (rest >> 1) & 3;
    int tau = (rest >> 3) % 5;
    int mt  = rest / 40;
    int ob  = mt * 16 + (lane >> 2);
    int kb  = kc * 16 + (lane & 3) * 2;

    const int dr[4] = {0, 8, 0, 8};
    const int dk[4] = {0, 0, 8, 8};
    uint32_t regs[4];
    #pragma unroll
    for (int r = 0; r < 4; r++) {
        int o = ob + dr[r];
        uint16_t pk[2];
        #pragma unroll
        for (int e = 0; e < 2; e++) {
            int kk = kb + dk[r] + e;
            float w = 0.0f;
            if (kk < K_ * CIN) {
                int k = kk >> 3, i = kk & 7;
                w = W[((k * TKS + tau) * CIN + i) * COUT + o];
            }
            __nv_bfloat16 h = __float2bfloat16(w);
            if (ws) h = __float2bfloat16(w - __bfloat162float(h));
            pk[e] = *reinterpret_cast<uint16_t*>(&h);
        }
        regs[r] = (uint32_t)pk[0] | ((uint32_t)pk[1] << 16);
    }
    g_wfrag[idx] = make_uint4(regs[0], regs[1], regs[2], regs[3]);
}

// HMMA m16n8k16 bf16 -> f32 accumulate
__device__ __forceinline__ void mma16816(float* c, uint4 a, uint32_t b0, uint32_t b1)
{
    asm("mma.sync.aligned.m16n8k16.row.col.f32.bf16.bf16.f32 "
        "{%0,%1,%2,%3}, {%4,%5,%6,%7}, {%8,%9}, {%0,%1,%2,%3};"
        : "+f"(c[0]), "+f"(c[1]), "+f"(c[2]), "+f"(c[3])
        : "r"(a.x), "r"(a.y), "r"(a.z), "r"(a.w), "r"(b0), "r"(b1));
}

// ---------------------------------------------------------------------------
// Main kernel. CTA = (l, group of 4 b's), 4 warps, warp = one b (slot).
// X SMEM: [slot][row t][col kk] bf16, row stride 144 B, hi and lo splits.
// out[o, t] = sum over pass/tau/kk of Wfrag . Xfrag with tau as row offset.
// ---------------------------------------------------------------------------
__global__ void __launch_bounds__(128, 4)
indexed_conv_hmma(const float* __restrict__ x,
                  const int*   __restrict__ nidx,
                  const float* __restrict__ bias,
                  float*       __restrict__ out)
{
    extern __shared__ unsigned char sm[];
    __shared__ int sj[K_], smask[K_];

    const int tid = threadIdx.x;
    const int l   = blockIdx.x;
    const int bg  = blockIdx.y;

    if (tid < K_) {
        int j = nidx[l * K_ + tid];
        sj[tid]    = (j >= 0) ? j : 0;
        smask[tid] = (j >= 0) ? 1 : 0;
    }
    // zero X (pads, masked-k regions, kk 56..63 must be 0)
    {
        uint4 z = make_uint4(0, 0, 0, 0);
        uint4* p = reinterpret_cast<uint4*>(sm);
        for (int q = tid; q < X_TOTAL / 16; q += 128) p[q] = z;
    }
    __syncthreads();

    // Gather + bf16 hi/lo split. Task q -> (slot, k, t): 8 floats -> 2 STS.128.
    for (int q = tid; q < NSLOT * K_ * T_; q += 128) {
        int slot = q / (K_ * T_);
        int r    = q - slot * (K_ * T_);
        int k    = r / T_;
        int t    = r - k * T_;
        if (!smask[k]) continue;
        const float4* src = reinterpret_cast<const float4*>(
            x + (((size_t)(bg * NSLOT + slot) * L_ + sj[k]) * T_ + t) * CIN);
        float4 v0 = src[0], v1 = src[1];
        __nv_bfloat162 h0 = __float22bfloat162_rn(make_float2(v0.x, v0.y));
        __nv_bfloat162 h1 = __float22bfloat162_rn(make_float2(v0.z, v0.w));
        __nv_bfloat162 h2 = __float22bfloat162_rn(make_float2(v1.x, v1.y));
        __nv_bfloat162 h3 = __float22bfloat162_rn(make_float2(v1.z, v1.w));
        __nv_bfloat162 l0 = __float22bfloat162_rn(make_float2(v0.x - __low2float(h0), v0.y - __high2float(h0)));
        __nv_bfloat162 l1 = __float22bfloat162_rn(make_float2(v0.z - __low2float(h1), v0.w - __high2float(h1)));
        __nv_bfloat162 l2 = __float22bfloat162_rn(make_float2(v1.x - __low2float(h2), v1.y - __high2float(h2)));
        __nv_bfloat162 l3 = __float22bfloat162_rn(make_float2(v1.z - __low2float(h3), v1.w - __high2float(h3)));
        int off = slot * XSLOT + t * XSTRIDE + k * 16;
        *reinterpret_cast<uint4*>(sm + off) =
            make_uint4(*reinterpret_cast<uint32_t*>(&h0), *reinterpret_cast<uint32_t*>(&h1),
                       *reinterpret_cast<uint32_t*>(&h2), *reinterpret_cast<uint32_t*>(&h3));
        *reinterpret_cast<uint4*>(sm + OFF_XLO + off) =
            make_uint4(*reinterpret_cast<uint32_t*>(&l0), *reinterpret_cast<uint32_t*>(&l1),
                       *reinterpret_cast<uint32_t*>(&l2), *reinterpret_cast<uint32_t*>(&l3));
    }
    __syncthreads();

    // ---- compute: warp w handles slot w ----
    const int w    = tid >> 5;
    const int lane = tid & 31;
    const unsigned char* xhi = sm + w * XSLOT;
    const unsigned char* xlo = sm + OFF_XLO + w * XSLOT;
    const uint32_t laneoff = (uint32_t)((lane >> 2) * XSTRIDE + (lane & 3) * 4);

    float acc[2][5][4];
    #pragma unroll
    for (int mt = 0; mt < 2; mt++)
        #pragma unroll
        for (int nt = 0; nt < 5; nt++)
            #pragma unroll
            for (int c = 0; c < 4; c++) acc[mt][nt][c] = 0.0f;

    #pragma unroll 1
    for (int pass = 0; pass < 3; pass++) {
        const unsigned char* xb = (pass == 2) ? xlo : xhi;
        const int ws = (pass == 1) ? 1 : 0;
        #pragma unroll
        for (int tau = 0; tau < TKS; tau++) {
            #pragma unroll
            for (int kc = 0; kc < 4; kc++) {
                uint4 A0 = g_wfrag[(((0 * 5 + tau) * 4 + kc) * 2 + ws) * 32 + lane];
                uint4 A1 = g_wfrag[(((1 * 5 + tau) * 4 + kc) * 2 + ws) * 32 + lane];
                const unsigned char* bp = xb + tau * XSTRIDE + kc * 32 + laneoff;
                #pragma unroll
                for (int nt = 0; nt < 5; nt++) {
                    uint32_t b0 = *reinterpret_cast<const uint32_t*>(bp + nt * (8 * XSTRIDE));
                    uint32_t b1 = *reinterpret_cast<const uint32_t*>(bp + nt * (8 * XSTRIDE) + 16);
                    mma16816(acc[0][nt], A0, b0, b1);
                    mma16816(acc[1][nt], A1, b0, b1);
                }
            }
        }
    }

    // ---- epilogue: C frag (o = M rows, t = N cols) + bias, masked t < 36 ----
    const int b = bg * NSLOT + w;
    float* ob = out + ((size_t)b * L_ + l) * TOUT * COUT;
    const int o0 = lane >> 2;
    const int tc = (lane & 3) * 2;
    #pragma unroll
    for (int mt = 0; mt < 2; mt++) {
        const int o = mt * 16 + o0;
        const float bv0 = bias[o];
        const float bv8 = bias[o + 8];
        #pragma unroll
        for (int nt = 0; nt < 5; nt++) {
            const int t0 = nt * 8 + tc;
            const float* c = acc[mt][nt];
            if (t0 < TOUT) {
                ob[t0 * COUT + o]     = c[0] + bv0;
                ob[t0 * COUT + o + 8] = c[2] + bv8;
            }
            if (t0 + 1 < TOUT) {
                ob[(t0 + 1) * COUT + o]     = c[1] + bv0;
                ob[(t0 + 1) * COUT + o + 8] = c[3] + bv8;
            }
        }
    }
}

extern "C" void kernel_launch(void* const* d_in, const int* in_sizes, int n_in,
                              void* d_out, int out_size)
{
    const float* x    = (const float*)d_in[0];
    const int*   nidx = (const int*)  d_in[1];
    const float* W    = (const float*)d_in[2];
    const float* bias = (const float*)d_in[3];
    float*       out  = (float*)d_out;

    cudaFuncSetAttribute(indexed_conv_hmma,
                         cudaFuncAttributeMaxDynamicSharedMemorySize, SMEM_DYN);

    wfrag_kernel<<<(NFRAG + 255) / 256, 256>>>(W);
    dim3 grid(L_, B_ / NSLOT);
    indexed_conv_hmma<<<grid, 128, SMEM_DYN>>>(x, nidx, bias, out);
}

// round 8
// speedup vs baseline: 3.0066x; 1.6264x over previous
#include <cuda_runtime.h>
#include <cuda_fp16.h>
#include <cstdint>

// Problem constants
#define B_    32
#define L_    1855
#define K_    7
#define T_    40
#define CIN   8
#define COUT  32
#define TKS   5
#define TOUT  36

// Tiling
#define NSLOT   4                 // b's per CTA (one warp each)
#define XROWS   48                // 40 data rows + pad (window reach 43)
#define XSTRIDE 144               // bytes/row: 64 fp16 = 128 B + 16 B pad
#define XSLOT   (XROWS * XSTRIDE) // 6912 B per slot (hi split only)
#define X_TOTAL (NSLOT * XSLOT)   // 27648
#define SMEM_DYN (X_TOTAL)

// W fragments: [tau(5)][kc(4)][j(4): mt*2+ws] x 32 lanes, uint4 each = 40 KB
#define NFRAG (5 * 4 * 4 * 32)
__device__ uint4 g_wfrag[NFRAG];

// ---------------------------------------------------------------------------
// Pre-kernel: m16n8k16 A-fragments of W, fp16 hi/lo splits, per lane.
// A row-major M=o(16) x K=kk(16). reg r: (row + {0,8,0,8}, k0 + {0,0,8,8}).
// ---------------------------------------------------------------------------
__global__ void wfrag_kernel(const float* __restrict__ W)
{
    int idx = blockIdx.x * blockDim.x + threadIdx.x;
    if (idx >= NFRAG) return;
    int lane = idx & 31, rest = idx >> 5;    // rest = (tau*4 + kc)*4 + j
    int j   = rest & 3;                      // j = mt*2 + ws
    int kc  = (rest >> 2) & 3;
    int tau = rest >> 4;
    int mt  = j >> 1, ws = j & 1;
    int ob  = mt * 16 + (lane >> 2);
    int kb  = kc * 16 + (lane & 3) * 2;

    const int dr[4] = {0, 8, 0, 8};
    const int dk[4] = {0, 0, 8, 8};
    uint32_t regs[4];
    #pragma unroll
    for (int r = 0; r < 4; r++) {
        int o = ob + dr[r];
        uint16_t pk[2];
        #pragma unroll
        for (int e = 0; e < 2; e++) {
            int kk = kb + dk[r] + e;
            float w = 0.0f;
            if (kk < K_ * CIN) {
                int k = kk >> 3, i = kk & 7;
                w = W[((k * TKS + tau) * CIN + i) * COUT + o];
            }
            __half h = __float2half_rn(w);
            if (ws) h = __float2half_rn(w - __half2float(h));
            pk[e] = *reinterpret_cast<uint16_t*>(&h);
        }
        regs[r] = (uint32_t)pk[0] | ((uint32_t)pk[1] << 16);
    }
    g_wfrag[idx] = make_uint4(regs[0], regs[1], regs[2], regs[3]);
}

// HMMA m16n8k16 fp16 -> f32 accumulate
__device__ __forceinline__ void mma16816(float* c, uint4 a, uint32_t b0, uint32_t b1)
{
    asm("mma.sync.aligned.m16n8k16.row.col.f32.f16.f16.f32 "
        "{%0,%1,%2,%3}, {%4,%5,%6,%7}, {%8,%9}, {%0,%1,%2,%3};"
        : "+f"(c[0]), "+f"(c[1]), "+f"(c[2]), "+f"(c[3])
        : "r"(a.x), "r"(a.y), "r"(a.z), "r"(a.w), "r"(b0), "r"(b1));
}
__device__ __forceinline__ void ldsm_x4(uint32_t& r0, uint32_t& r1,
                                        uint32_t& r2, uint32_t& r3, uint32_t a)
{
    asm volatile("ldmatrix.sync.aligned.m8n8.x4.shared.b16 {%0,%1,%2,%3}, [%4];"
                 : "=r"(r0), "=r"(r1), "=r"(r2), "=r"(r3) : "r"(a));
}
__device__ __forceinline__ void ldsm_x2(uint32_t& r0, uint32_t& r1, uint32_t a)
{
    asm volatile("ldmatrix.sync.aligned.m8n8.x2.shared.b16 {%0,%1}, [%2];"
                 : "=r"(r0), "=r"(r1) : "r"(a));
}
__device__ __forceinline__ uint32_t smem_u32(const void* p) {
    uint32_t a;
    asm("{ .reg .u64 t; cvta.to.shared.u64 t, %1; cvt.u32.u64 %0, t; }" : "=r"(a) : "l"(p));
    return a;
}

// ---------------------------------------------------------------------------
// Main kernel. CTA = (l, group of 4 b's), 4 warps, warp = one b (slot).
// X SMEM (fp16 hi only): [slot][t][kk], row stride 144 B.
// 2 split passes share B operands: acc += A_hi.B; acc += A_lo.B.
// ---------------------------------------------------------------------------
__global__ void __launch_bounds__(128, 6)
indexed_conv_hmma(const float* __restrict__ x,
                  const int*   __restrict__ nidx,
                  const float* __restrict__ bias,
                  float*       __restrict__ out)
{
    extern __shared__ unsigned char sm[];
    __shared__ int sj[K_], smask[K_];

    const int tid = threadIdx.x;
    const int l   = blockIdx.x;
    const int bg  = blockIdx.y;

    if (tid < K_) {
        int j = nidx[l * K_ + tid];
        sj[tid]    = (j >= 0) ? j : 0;
        smask[tid] = (j >= 0) ? 1 : 0;
    }
    {   // zero X (pads, masked-k, kk 56..63, rows 40..47)
        uint4 z = make_uint4(0, 0, 0, 0);
        uint4* p = reinterpret_cast<uint4*>(sm);
        for (int q = tid; q < X_TOTAL / 16; q += 128) p[q] = z;
    }
    __syncthreads();

    // Gather + fp16 convert (hi split only): task q -> (slot,k,t), one STS.128.
    for (int q = tid; q < NSLOT * K_ * T_; q += 128) {
        int slot = q / (K_ * T_);
        int r    = q - slot * (K_ * T_);
        int k    = r / T_;
        int t    = r - k * T_;
        if (!smask[k]) continue;
        const float4* src = reinterpret_cast<const float4*>(
            x + (((size_t)(bg * NSLOT + slot) * L_ + sj[k]) * T_ + t) * CIN);
        float4 v0 = src[0], v1 = src[1];
        __half2 h0 = __floats2half2_rn(v0.x, v0.y);
        __half2 h1 = __floats2half2_rn(v0.z, v0.w);
        __half2 h2 = __floats2half2_rn(v1.x, v1.y);
        __half2 h3 = __floats2half2_rn(v1.z, v1.w);
        *reinterpret_cast<uint4*>(sm + slot * XSLOT + t * XSTRIDE + k * 16) =
            make_uint4(*reinterpret_cast<uint32_t*>(&h0), *reinterpret_cast<uint32_t*>(&h1),
                       *reinterpret_cast<uint32_t*>(&h2), *reinterpret_cast<uint32_t*>(&h3));
    }
    __syncthreads();

    // ---- compute: warp w handles slot w ----
    const int w    = tid >> 5;
    const int lane = tid & 31;
    const int r8   = lane & 7;
    const int m    = lane >> 3;

    const uint32_t xb = smem_u32(sm) + w * XSLOT;
    // ldmatrix row-address bases (per lane): matrix m -> (nt = g*2 + (m>>1), kh = m&1)
    const uint32_t a4_0 = xb + (((m >> 1) * 8 + r8) * XSTRIDE) + (m & 1) * 16;       // nt 0,1
    const uint32_t a4_1 = xb + (((2 + (m >> 1)) * 8 + r8) * XSTRIDE) + (m & 1) * 16; // nt 2,3
    const uint32_t a2   = xb + ((32 + r8) * XSTRIDE) + (m & 1) * 16;                 // nt 4

    // acc init with bias: c0,c1 -> o; c2,c3 -> o+8
    float acc[2][5][4];
    {
        const int o0 = lane >> 2;
        #pragma unroll
        for (int mt = 0; mt < 2; mt++) {
            float bv0 = bias[mt * 16 + o0];
            float bv8 = bias[mt * 16 + o0 + 8];
            #pragma unroll
            for (int nt = 0; nt < 5; nt++) {
                acc[mt][nt][0] = bv0; acc[mt][nt][1] = bv0;
                acc[mt][nt][2] = bv8; acc[mt][nt][3] = bv8;
            }
        }
    }

    #pragma unroll
    for (int tau = 0; tau < TKS; tau++) {
        #pragma unroll
        for (int kc = 0; kc < 4; kc++) {
            const uint32_t ofs = tau * XSTRIDE + kc * 32;
            uint32_t Bf[10];
            ldsm_x4(Bf[0], Bf[1], Bf[2], Bf[3], a4_0 + ofs);
            ldsm_x4(Bf[4], Bf[5], Bf[6], Bf[7], a4_1 + ofs);
            ldsm_x2(Bf[8], Bf[9], a2 + ofs);
            const uint4* wf = g_wfrag + ((tau * 4 + kc) * 4) * 32 + lane;
            uint4 A00 = wf[0];      // mt0 hi
            uint4 A01 = wf[32];     // mt0 lo
            uint4 A10 = wf[64];     // mt1 hi
            uint4 A11 = wf[96];     // mt1 lo
            #pragma unroll
            for (int nt = 0; nt < 5; nt++) {
                uint32_t b0 = Bf[nt * 2], b1 = Bf[nt * 2 + 1];
                mma16816(acc[0][nt], A00, b0, b1);
                mma16816(acc[0][nt], A01, b0, b1);
                mma16816(acc[1][nt], A10, b0, b1);
                mma16816(acc[1][nt], A11, b0, b1);
            }
        }
    }

    // ---- epilogue: C frag (o rows, t cols), masked t < 36 ----
    const int b = bg * NSLOT + w;
    float* ob = out + ((size_t)b * L_ + l) * TOUT * COUT;
    const int o0 = lane >> 2;
    const int tc = (lane & 3) * 2;
    #pragma unroll
    for (int mt = 0; mt < 2; mt++) {
        const int o = mt * 16 + o0;
        #pragma unroll
        for (int nt = 0; nt < 5; nt++) {
            const int t0 = nt * 8 + tc;
            const float* c = acc[mt][nt];
            if (t0 < TOUT) {
                ob[t0 * COUT + o]     = c[0];
                ob[t0 * COUT + o + 8] = c[2];
            }
            if (t0 + 1 < TOUT) {
                ob[(t0 + 1) * COUT + o]     = c[1];
                ob[(t0 + 1) * COUT + o + 8] = c[3];
            }
        }
    }
}

extern "C" void kernel_launch(void* const* d_in, const int* in_sizes, int n_in,
                              void* d_out, int out_size)
{
    const float* x    = (const float*)d_in[0];
    const int*   nidx = (const int*)  d_in[1];
    const float* W    = (const float*)d_in[2];
    const float* bias = (const float*)d_in[3];
    float*       out  = (float*)d_out;

    cudaFuncSetAttribute(indexed_conv_hmma,
                         cudaFuncAttributeMaxDynamicSharedMemorySize, SMEM_DYN);

    wfrag_kernel<<<(NFRAG + 255) / 256, 256>>>(W);
    dim3 grid(L_, B_ / NSLOT);
    indexed_conv_hmma<<<grid, 128, SMEM_DYN>>>(x, nidx, bias, out);
}

// round 11
// speedup vs baseline: 3.1728x; 1.0553x over previous
#include <cuda_runtime.h>
#include <cuda_fp16.h>
#include <cstdint>

// Problem constants
#define B_    32
#define L_    1855
#define K_    7
#define T_    40
#define CIN   8
#define COUT  32
#define TKS   5
#define TOUT  36

// Tiling
#define NSLOT   8                 // b's per CTA; warp handles 2 (N=72 fused)
#define XSTRIDE 144               // bytes/row: 56 fp16 = 112 B data, pad to 144
#define XROWS   40
#define XSLOT   (XROWS * XSTRIDE) // 5760 B per slot
#define X_TOTAL (NSLOT * XSLOT)   // 46080
#define SMEM_DYN X_TOTAL

// W fragments, k16 chunks: [tau(5)][kc(3)][j(4)=mt*2+ws] x 32 lanes (uint4)
#define NF16 (5 * 3 * 4 * 32)
// W fragments, k8 chunk (kk48-55): [tau(5)][j(4)] x 32 lanes (uint2)
#define NF8  (5 * 4 * 32)
__device__ uint4 g_wfrag16[NF16];
__device__ uint2 g_wfrag8[NF8];

// ---------------------------------------------------------------------------
// Pre-kernel: A-fragments of W (fp16 hi/lo splits).
// m16n8k16: reg r holds (row + {0,8,0,8}, k0 + {0,0,8,8}), k0=(lane&3)*2.
// m16n8k8:  reg r holds (row + {0,8}, k0..k0+1).
// ---------------------------------------------------------------------------
__global__ void wfrag_kernel(const float* __restrict__ W)
{
    int idx = blockIdx.x * blockDim.x + threadIdx.x;
    if (idx < NF16) {
        int lane = idx & 31, rest = idx >> 5;   // rest = (tau*3 + kc)*4 + j
        int j   = rest & 3;
        int kc  = (rest >> 2) % 3;
        int tau = rest / 12;
        int mt  = j >> 1, ws = j & 1;
        int ob  = mt * 16 + (lane >> 2);
        int kb  = kc * 16 + (lane & 3) * 2;
        const int dr[4] = {0, 8, 0, 8};
        const int dk[4] = {0, 0, 8, 8};
        uint32_t regs[4];
        #pragma unroll
        for (int r = 0; r < 4; r++) {
            uint16_t pk[2];
            #pragma unroll
            for (int e = 0; e < 2; e++) {
                int kk = kb + dk[r] + e;
                int k = kk >> 3, i = kk & 7;
                float w = W[((k * TKS + tau) * CIN + i) * COUT + (ob + dr[r])];
                __half h = __float2half_rn(w);
                if (ws) h = __float2half_rn(w - __half2float(h));
                pk[e] = *reinterpret_cast<uint16_t*>(&h);
            }
            regs[r] = (uint32_t)pk[0] | ((uint32_t)pk[1] << 16);
        }
        g_wfrag16[idx] = make_uint4(regs[0], regs[1], regs[2], regs[3]);
    } else if (idx < NF16 + NF8) {
        int i2 = idx - NF16;
        int lane = i2 & 31, rest = i2 >> 5;     // rest = tau*4 + j
        int j = rest & 3, tau = rest >> 2;
        int mt = j >> 1, ws = j & 1;
        uint32_t regs[2];
        #pragma unroll
        for (int r = 0; r < 2; r++) {
            int o = mt * 16 + (lane >> 2) + r * 8;
            uint16_t pk[2];
            #pragma unroll
            for (int e = 0; e < 2; e++) {
                int kk = 48 + (lane & 3) * 2 + e;
                int k = kk >> 3, i = kk & 7;
                float w = W[((k * TKS + tau) * CIN + i) * COUT + o];
                __half h = __float2half_rn(w);
                if (ws) h = __float2half_rn(w - __half2float(h));
                pk[e] = *reinterpret_cast<uint16_t*>(&h);
            }
            regs[r] = (uint32_t)pk[0] | ((uint32_t)pk[1] << 16);
        }
        g_wfrag8[i2] = make_uint2(regs[0], regs[1]);
    }
}

// ---------------- mma / ldmatrix helpers ----------------
__device__ __forceinline__ void mma16816(float* c, uint4 a, uint32_t b0, uint32_t b1)
{
    asm("mma.sync.aligned.m16n8k16.row.col.f32.f16.f16.f32 "
        "{%0,%1,%2,%3}, {%4,%5,%6,%7}, {%8,%9}, {%0,%1,%2,%3};"
        : "+f"(c[0]), "+f"(c[1]), "+f"(c[2]), "+f"(c[3])
        : "r"(a.x), "r"(a.y), "r"(a.z), "r"(a.w), "r"(b0), "r"(b1));
}
__device__ __forceinline__ void mma1688(float* c, uint2 a, uint32_t b0)
{
    asm("mma.sync.aligned.m16n8k8.row.col.f32.f16.f16.f32 "
        "{%0,%1,%2,%3}, {%4,%5}, {%6}, {%0,%1,%2,%3};"
        : "+f"(c[0]), "+f"(c[1]), "+f"(c[2]), "+f"(c[3])
        : "r"(a.x), "r"(a.y), "r"(b0));
}
__device__ __forceinline__ void ldsm_x4(uint32_t& r0, uint32_t& r1,
                                        uint32_t& r2, uint32_t& r3, uint32_t a)
{
    asm volatile("ldmatrix.sync.aligned.m8n8.x4.shared.b16 {%0,%1,%2,%3}, [%4];"
                 : "=r"(r0), "=r"(r1), "=r"(r2), "=r"(r3) : "r"(a));
}
__device__ __forceinline__ void ldsm_x2(uint32_t& r0, uint32_t& r1, uint32_t a)
{
    asm volatile("ldmatrix.sync.aligned.m8n8.x2.shared.b16 {%0,%1}, [%2];"
                 : "=r"(r0), "=r"(r1) : "r"(a));
}
__device__ __forceinline__ void ldsm_x1(uint32_t& r0, uint32_t a)
{
    asm volatile("ldmatrix.sync.aligned.m8n8.x1.shared.b16 {%0}, [%1];"
                 : "=r"(r0) : "r"(a));
}
__device__ __forceinline__ uint32_t smem_u32(const void* p) {
    uint32_t a;
    asm("{ .reg .u64 t; cvta.to.shared.u64 t, %1; cvt.u32.u64 %0, t; }" : "=r"(a) : "l"(p));
    return a;
}

// ---------------------------------------------------------------------------
// Main kernel. CTA = (l, group of 8 b's); warp w handles slots 2w, 2w+1 fused
// in the N dimension: N = 72 = 9 n8 tiles (tile n -> slotA t=n if n<36 else
// slotB t=n-36). tau realized as uniform +tau*XSTRIDE address offset.
// K = 56 = 3 x k16 chunks + 1 x k8 chunk (kk48-55). 2 split passes (W hi/lo).
// ---------------------------------------------------------------------------
__global__ void __launch_bounds__(128, 4)
indexed_conv_hmma(const float* __restrict__ x,
                  const int*   __restrict__ nidx,
                  const float* __restrict__ bias,
                  float*       __restrict__ out)
{
    extern __shared__ unsigned char sm[];
    __shared__ int sj[K_], smask[K_];

    const int tid = threadIdx.x;
    const int l   = blockIdx.x;
    const int bg  = blockIdx.y;

    if (tid < K_) {
        int j = nidx[l * K_ + tid];
        sj[tid]    = (j >= 0) ? j : 0;
        smask[tid] = (j >= 0) ? 1 : 0;
    }
    __syncthreads();

    // Gather + fp16 convert. Every (slot,k,t) written (zeros when masked), so
    // no separate zero-fill pass. Covers t 0..39, kk 0..55.
    for (int q = tid; q < NSLOT * K_ * T_; q += 128) {
        int slot = q / (K_ * T_);
        int r    = q - slot * (K_ * T_);
        int k    = r / T_;
        int t    = r - k * T_;
        uint4 pkt = make_uint4(0, 0, 0, 0);
        if (smask[k]) {
            const float4* src = reinterpret_cast<const float4*>(
                x + (((size_t)(bg * NSLOT + slot) * L_ + sj[k]) * T_ + t) * CIN);
            float4 v0 = src[0], v1 = src[1];
            __half2 h0 = __floats2half2_rn(v0.x, v0.y);
            __half2 h1 = __floats2half2_rn(v0.z, v0.w);
            __half2 h2 = __floats2half2_rn(v1.x, v1.y);
            __half2 h3 = __floats2half2_rn(v1.z, v1.w);
            pkt = make_uint4(*reinterpret_cast<uint32_t*>(&h0), *reinterpret_cast<uint32_t*>(&h1),
                             *reinterpret_cast<uint32_t*>(&h2), *reinterpret_cast<uint32_t*>(&h3));
        }
        *reinterpret_cast<uint4*>(sm + slot * XSLOT + t * XSTRIDE + k * 16) = pkt;
    }
    __syncthreads();

    // ---- per-lane ldmatrix base addresses ----
    const int w    = tid >> 5;
    const int lane = tid & 31;
    const int r8   = lane & 7;
    const uint32_t xb = smem_u32(sm) + w * 2 * XSLOT;

    // n -> address of (slot, t) row
    auto naddr = [&](int n, int colbyte) -> uint32_t {
        int s = (n >= 36);
        int t = n - 36 * s;
        return xb + s * XSLOT + t * XSTRIDE + colbyte;
    };

    uint32_t b16b[5], b8b[3];
    {
        const int m = lane >> 3;
        #pragma unroll
        for (int g = 0; g < 4; g++) {   // x4: matrices (tile 2g+(m>>1), khalf m&1)
            int tile = 2 * g + (m >> 1);
            b16b[g] = naddr(tile * 8 + r8, (m & 1) * 16);
        }
        b16b[4] = naddr(64 + r8, ((lane >> 3) & 1) * 16);     // x2: tile 8
        #pragma unroll
        for (int g = 0; g < 2; g++)     // k8 x4: matrices = tiles 4g+m
            b8b[g] = naddr((4 * g + m) * 8 + r8, 96);
        b8b[2] = naddr(64 + r8, 96);                          // k8 x1: tile 8
    }

    // acc init with bias
    float acc[2][9][4];
    {
        const int o0 = lane >> 2;
        #pragma unroll
        for (int mt = 0; mt < 2; mt++) {
            float bv0 = bias[mt * 16 + o0];
            float bv8 = bias[mt * 16 + o0 + 8];
            #pragma unroll
            for (int nt = 0; nt < 9; nt++) {
                acc[mt][nt][0] = bv0; acc[mt][nt][1] = bv0;
                acc[mt][nt][2] = bv8; acc[mt][nt][3] = bv8;
            }
        }
    }

    #pragma unroll
    for (int tau = 0; tau < TKS; tau++) {
        // k16 chunks
        #pragma unroll
        for (int kc = 0; kc < 3; kc++) {
            const uint32_t ofs = tau * XSTRIDE + kc * 32;
            const uint4* wf = g_wfrag16 + ((tau * 3 + kc) * 4) * 32 + lane;
            uint4 A00 = wf[0], A01 = wf[32], A10 = wf[64], A11 = wf[96];
            #pragma unroll
            for (int g = 0; g < 4; g++) {
                uint32_t B0, B1, B2, B3;
                ldsm_x4(B0, B1, B2, B3, b16b[g] + ofs);
                const int ta = 2 * g, tb = 2 * g + 1;
                mma16816(acc[0][ta], A00, B0, B1);
                mma16816(acc[1][ta], A10, B0, B1);
                mma16816(acc[0][ta], A01, B0, B1);
                mma16816(acc[1][ta], A11, B0, B1);
                mma16816(acc[0][tb], A00, B2, B3);
                mma16816(acc[1][tb], A10, B2, B3);
                mma16816(acc[0][tb], A01, B2, B3);
                mma16816(acc[1][tb], A11, B2, B3);
            }
            {
                uint32_t B0, B1;
                ldsm_x2(B0, B1, b16b[4] + ofs);
                mma16816(acc[0][8], A00, B0, B1);
                mma16816(acc[1][8], A10, B0, B1);
                mma16816(acc[0][8], A01, B0, B1);
                mma16816(acc[1][8], A11, B0, B1);
            }
        }
        // k8 chunk (kk 48..55)
        {
            const uint32_t ofs = tau * XSTRIDE;
            const uint2* wf = g_wfrag8 + (tau * 4) * 32 + lane;
            uint2 A00 = wf[0], A01 = wf[32], A10 = wf[64], A11 = wf[96];
            #pragma unroll
            for (int g = 0; g < 2; g++) {
                uint32_t B0, B1, B2, B3;
                ldsm_x4(B0, B1, B2, B3, b8b[g] + ofs);
                const int t0 = 4 * g;
                mma1688(acc[0][t0 + 0], A00, B0);
                mma1688(acc[1][t0 + 0], A10, B0);
                mma1688(acc[0][t0 + 0], A01, B0);
                mma1688(acc[1][t0 + 0], A11, B0);
                mma1688(acc[0][t0 + 1], A00, B1);
                mma1688(acc[1][t0 + 1], A10, B1);
                mma1688(acc[0][t0 + 1], A01, B1);
                mma1688(acc[1][t0 + 1], A11, B1);
                mma1688(acc[0][t0 + 2], A00, B2);
                mma1688(acc[1][t0 + 2], A10, B2);
                mma1688(acc[0][t0 + 2], A01, B2);
                mma1688(acc[1][t0 + 2], A11, B2);
                mma1688(acc[0][t0 + 3], A00, B3);
                mma1688(acc[1][t0 + 3], A10, B3);
                mma1688(acc[0][t0 + 3], A01, B3);
                mma1688(acc[1][t0 + 3], A11, B3);
            }
            {
                uint32_t B0;
                ldsm_x1(B0, b8b[2] + ofs);
                mma1688(acc[0][8], A00, B0);
                mma1688(acc[1][8], A10, B0);
                mma1688(acc[0][8], A01, B0);
                mma1688(acc[1][8], A11, B0);
            }
        }
    }

    // ---- epilogue: n -> (slot, t); all n in [0,72) valid, no masking ----
    const int o0 = lane >> 2;
    const int tc = (lane & 3) * 2;
    #pragma unroll
    for (int nt = 0; nt < 9; nt++) {
        const int n0  = nt * 8 + tc;
        const int s   = (n0 >= 36);
        const int t0  = n0 - 36 * s;
        const int b   = bg * NSLOT + 2 * w + s;
        float* ob = out + (((size_t)b * L_ + l) * TOUT + t0) * COUT;
        #pragma unroll
        for (int mt = 0; mt < 2; mt++) {
            const int o = mt * 16 + o0;
            const float* c = acc[mt][nt];
            ob[o]            = c[0];
            ob[o + 8]        = c[2];
            ob[COUT + o]     = c[1];
            ob[COUT + o + 8] = c[3];
        }
    }
}

extern "C" void kernel_launch(void* const* d_in, const int* in_sizes, int n_in,
                              void* d_out, int out_size)
{
    const float* x    = (const float*)d_in[0];
    const int*   nidx = (const int*)  d_in[1];
    const float* W    = (const float*)d_in[2];
    const float* bias = (const float*)d_in[3];
    float*       out  = (float*)d_out;

    cudaFuncSetAttribute(indexed_conv_hmma,
                         cudaFuncAttributeMaxDynamicSharedMemorySize, SMEM_DYN);

    wfrag_kernel<<<(NF16 + NF8 + 255) / 256, 256>>>(W);
    dim3 grid(L_, B_ / NSLOT);
    indexed_conv_hmma<<<grid, 128, SMEM_DYN>>>(x, nidx, bias, out);
}

// round 14
// speedup vs baseline: 3.7133x; 1.1703x over previous
#include <cuda_runtime.h>
#include <cuda_fp16.h>
#include <cstdint>

// Problem constants
#define B_    32
#define L_    1855
#define K_    7
#define T_    40
#define CIN   8
#define COUT  32
#define TKS   5
#define TOUT  36

// Tiling
#define NSLOT   8                 // b's per CTA; warp handles 2 (N=72 fused)
#define XSTRIDE 144               // bytes/row: 56 fp16 = 112 B data, pad to 144
#define XROWS   40
#define XSLOT   (XROWS * XSTRIDE) // 5760 B per slot
#define X_TOTAL (NSLOT * XSLOT)   // 46080
#define SMEM_DYN X_TOTAL
// epilogue staging: per-warp [slot(2)][t(36)][o(32)] f32, row stride 144 B
#define SSLOT   (36 * 144)        // 5184 B per slot
#define SWARP   (2 * SSLOT)       // 10368 B per warp (4*10368 = 41472 < 46080)

// W fragments (fp16, single hi pass)
// k16 chunks: [tau(5)][kc(3)][mt(2)] x 32 lanes (uint4)
#define NF16 (5 * 3 * 2 * 32)
// k8 chunk (kk48-55): [tau(5)][mt(2)] x 32 lanes (uint2)
#define NF8  (5 * 2 * 32)
__device__ uint4 g_wfrag16[NF16];
__device__ uint2 g_wfrag8[NF8];

// ---------------------------------------------------------------------------
// Pre-kernel: m16n8k16 / m16n8k8 A-fragments of W (fp16).
// m16n8k16 reg r: (row + {0,8,0,8}, k0 + {0,0,8,8}), k0=(lane&3)*2.
// ---------------------------------------------------------------------------
__global__ void wfrag_kernel(const float* __restrict__ W)
{
    int idx = blockIdx.x * blockDim.x + threadIdx.x;
    if (idx < NF16) {
        int lane = idx & 31, rest = idx >> 5;   // rest = (tau*3 + kc)*2 + mt
        int mt  = rest & 1;
        int kc  = (rest >> 1) % 3;
        int tau = rest / 6;
        int ob  = mt * 16 + (lane >> 2);
        int kb  = kc * 16 + (lane & 3) * 2;
        const int dr[4] = {0, 8, 0, 8};
        const int dk[4] = {0, 0, 8, 8};
        uint32_t regs[4];
        #pragma unroll
        for (int r = 0; r < 4; r++) {
            uint16_t pk[2];
            #pragma unroll
            for (int e = 0; e < 2; e++) {
                int kk = kb + dk[r] + e;
                int k = kk >> 3, i = kk & 7;
                float w = W[((k * TKS + tau) * CIN + i) * COUT + (ob + dr[r])];
                __half h = __float2half_rn(w);
                pk[e] = *reinterpret_cast<uint16_t*>(&h);
            }
            regs[r] = (uint32_t)pk[0] | ((uint32_t)pk[1] << 16);
        }
        g_wfrag16[idx] = make_uint4(regs[0], regs[1], regs[2], regs[3]);
    } else if (idx < NF16 + NF8) {
        int i2 = idx - NF16;
        int lane = i2 & 31, rest = i2 >> 5;     // rest = tau*2 + mt
        int mt = rest & 1, tau = rest >> 1;
        uint32_t regs[2];
        #pragma unroll
        for (int r = 0; r < 2; r++) {
            int o = mt * 16 + (lane >> 2) + r * 8;
            uint16_t pk[2];
            #pragma unroll
            for (int e = 0; e < 2; e++) {
                int kk = 48 + (lane & 3) * 2 + e;
                int k = kk >> 3, i = kk & 7;
                float w = W[((k * TKS + tau) * CIN + i) * COUT + o];
                __half h = __float2half_rn(w);
                pk[e] = *reinterpret_cast<uint16_t*>(&h);
            }
            regs[r] = (uint32_t)pk[0] | ((uint32_t)pk[1] << 16);
        }
        g_wfrag8[i2] = make_uint2(regs[0], regs[1]);
    }
}

// ---------------- mma / ldmatrix helpers ----------------
__device__ __forceinline__ void mma16816(float* c, uint4 a, uint32_t b0, uint32_t b1)
{
    asm("mma.sync.aligned.m16n8k16.row.col.f32.f16.f16.f32 "
        "{%0,%1,%2,%3}, {%4,%5,%6,%7}, {%8,%9}, {%0,%1,%2,%3};"
        : "+f"(c[0]), "+f"(c[1]), "+f"(c[2]), "+f"(c[3])
        : "r"(a.x), "r"(a.y), "r"(a.z), "r"(a.w), "r"(b0), "r"(b1));
}
__device__ __forceinline__ void mma1688(float* c, uint2 a, uint32_t b0)
{
    asm("mma.sync.aligned.m16n8k8.row.col.f32.f16.f16.f32 "
        "{%0,%1,%2,%3}, {%4,%5}, {%6}, {%0,%1,%2,%3};"
        : "+f"(c[0]), "+f"(c[1]), "+f"(c[2]), "+f"(c[3])
        : "r"(a.x), "r"(a.y), "r"(b0));
}
__device__ __forceinline__ void ldsm_x4(uint32_t& r0, uint32_t& r1,
                                        uint32_t& r2, uint32_t& r3, uint32_t a)
{
    asm volatile("ldmatrix.sync.aligned.m8n8.x4.shared.b16 {%0,%1,%2,%3}, [%4];"
                 : "=r"(r0), "=r"(r1), "=r"(r2), "=r"(r3) : "r"(a));
}
__device__ __forceinline__ void ldsm_x2(uint32_t& r0, uint32_t& r1, uint32_t a)
{
    asm volatile("ldmatrix.sync.aligned.m8n8.x2.shared.b16 {%0,%1}, [%2];"
                 : "=r"(r0), "=r"(r1) : "r"(a));
}
__device__ __forceinline__ void ldsm_x1(uint32_t& r0, uint32_t a)
{
    asm volatile("ldmatrix.sync.aligned.m8n8.x1.shared.b16 {%0}, [%1];"
                 : "=r"(r0) : "r"(a));
}
__device__ __forceinline__ uint32_t smem_u32(const void* p) {
    uint32_t a;
    asm("{ .reg .u64 t; cvta.to.shared.u64 t, %1; cvt.u32.u64 %0, t; }" : "=r"(a) : "l"(p));
    return a;
}

// ---------------------------------------------------------------------------
// Main kernel. CTA = (l, group of 8 b's); warp w handles slots 2w, 2w+1 fused
// in the N dimension: N = 72 = 9 n8 tiles (tile n -> slotA t=n if n<36 else
// slotB t=n-36). tau realized as uniform +tau*XSTRIDE address offset.
// K = 56 = 3 x k16 + 1 x k8 (kk48-55). Single fp16 pass (W hi only).
// ---------------------------------------------------------------------------
__global__ void __launch_bounds__(128, 4)
indexed_conv_hmma(const float* __restrict__ x,
                  const int*   __restrict__ nidx,
                  const float* __restrict__ bias,
                  float*       __restrict__ out)
{
    extern __shared__ unsigned char sm[];
    __shared__ int sj[K_], smask[K_];

    const int tid = threadIdx.x;
    const int l   = blockIdx.x;
    const int bg  = blockIdx.y;

    if (tid < K_) {
        int j = nidx[l * K_ + tid];
        sj[tid]    = (j >= 0) ? j : 0;
        smask[tid] = (j >= 0) ? 1 : 0;
    }
    __syncthreads();

    // Gather + fp16 convert. Every (slot,k,t) written (zeros when masked).
    for (int q = tid; q < NSLOT * K_ * T_; q += 128) {
        int slot = q / (K_ * T_);
        int r    = q - slot * (K_ * T_);
        int k    = r / T_;
        int t    = r - k * T_;
        uint4 pkt = make_uint4(0, 0, 0, 0);
        if (smask[k]) {
            const float4* src = reinterpret_cast<const float4*>(
                x + (((size_t)(bg * NSLOT + slot) * L_ + sj[k]) * T_ + t) * CIN);
            float4 v0 = src[0], v1 = src[1];
            __half2 h0 = __floats2half2_rn(v0.x, v0.y);
            __half2 h1 = __floats2half2_rn(v0.z, v0.w);
            __half2 h2 = __floats2half2_rn(v1.x, v1.y);
            __half2 h3 = __floats2half2_rn(v1.z, v1.w);
            pkt = make_uint4(*reinterpret_cast<uint32_t*>(&h0), *reinterpret_cast<uint32_t*>(&h1),
                             *reinterpret_cast<uint32_t*>(&h2), *reinterpret_cast<uint32_t*>(&h3));
        }
        *reinterpret_cast<uint4*>(sm + slot * XSLOT + t * XSTRIDE + k * 16) = pkt;
    }
    __syncthreads();

    // ---- per-lane ldmatrix base addresses ----
    const int w    = tid >> 5;
    const int lane = tid & 31;
    const int r8   = lane & 7;
    const uint32_t xb = smem_u32(sm) + w * 2 * XSLOT;

    auto naddr = [&](int n, int colbyte) -> uint32_t {
        int s = (n >= 36);
        int t = n - 36 * s;
        return xb + s * XSLOT + t * XSTRIDE + colbyte;
    };

    uint32_t b16b[5], b8b[3];
    {
        const int m = lane >> 3;
        #pragma unroll
        for (int g = 0; g < 4; g++) {   // x4: matrices (tile 2g+(m>>1), khalf m&1)
            int tile = 2 * g + (m >> 1);
            b16b[g] = naddr(tile * 8 + r8, (m & 1) * 16);
        }
        b16b[4] = naddr(64 + r8, ((lane >> 3) & 1) * 16);     // x2: tile 8
        #pragma unroll
        for (int g = 0; g < 2; g++)     // k8 x4: matrices = tiles 4g+m
            b8b[g] = naddr((4 * g + m) * 8 + r8, 96);
        b8b[2] = naddr(64 + r8, 96);                          // k8 x1: tile 8
    }

    // acc init with bias
    float acc[2][9][4];
    {
        const int o0 = lane >> 2;
        #pragma unroll
        for (int mt = 0; mt < 2; mt++) {
            float bv0 = bias[mt * 16 + o0];
            float bv8 = bias[mt * 16 + o0 + 8];
            #pragma unroll
            for (int nt = 0; nt < 9; nt++) {
                acc[mt][nt][0] = bv0; acc[mt][nt][1] = bv0;
                acc[mt][nt][2] = bv8; acc[mt][nt][3] = bv8;
            }
        }
    }

    #pragma unroll
    for (int tau = 0; tau < TKS; tau++) {
        // k16 chunks
        #pragma unroll
        for (int kc = 0; kc < 3; kc++) {
            const uint32_t ofs = tau * XSTRIDE + kc * 32;
            const uint4* wf = g_wfrag16 + ((tau * 3 + kc) * 2) * 32 + lane;
            uint4 A0 = wf[0], A1 = wf[32];
            #pragma unroll
            for (int g = 0; g < 4; g++) {
                uint32_t B0, B1, B2, B3;
                ldsm_x4(B0, B1, B2, B3, b16b[g] + ofs);
                const int ta = 2 * g, tb = 2 * g + 1;
                mma16816(acc[0][ta], A0, B0, B1);
                mma16816(acc[1][ta], A1, B0, B1);
                mma16816(acc[0][tb], A0, B2, B3);
                mma16816(acc[1][tb], A1, B2, B3);
            }
            {
                uint32_t B0, B1;
                ldsm_x2(B0, B1, b16b[4] + ofs);
                mma16816(acc[0][8], A0, B0, B1);
                mma16816(acc[1][8], A1, B0, B1);
            }
        }
        // k8 chunk (kk 48..55)
        {
            const uint32_t ofs = tau * XSTRIDE;
            const uint2* wf = g_wfrag8 + (tau * 2) * 32 + lane;
            uint2 A0 = wf[0], A1 = wf[32];
            #pragma unroll
            for (int g = 0; g < 2; g++) {
                uint32_t B0, B1, B2, B3;
                ldsm_x4(B0, B1, B2, B3, b8b[g] + ofs);
                const int t0 = 4 * g;
                mma1688(acc[0][t0 + 0], A0, B0);
                mma1688(acc[1][t0 + 0], A1, B0);
                mma1688(acc[0][t0 + 1], A0, B1);
                mma1688(acc[1][t0 + 1], A1, B1);
                mma1688(acc[0][t0 + 2], A0, B2);
                mma1688(acc[1][t0 + 2], A1, B2);
                mma1688(acc[0][t0 + 3], A0, B3);
                mma1688(acc[1][t0 + 3], A1, B3);
            }
            {
                uint32_t B0;
                ldsm_x1(B0, b8b[2] + ofs);
                mma1688(acc[0][8], A0, B0);
                mma1688(acc[1][8], A1, B0);
            }
        }
    }

    // ---- epilogue: stage through SMEM for coalesced STG.128 ----
    __syncthreads();   // all warps done reading X (staging overlays X regions)

    unsigned char* stg = sm + w * SWARP;
    {
        const int o0  = lane >> 2;
        const int tc2 = (lane & 3) * 2;
        #pragma unroll
        for (int nt = 0; nt < 9; nt++) {
            const int n0 = nt * 8 + tc2;
            const int s  = (n0 >= 36);
            const int t0 = n0 - 36 * s;
            unsigned char* rp = stg + s * SSLOT + t0 * 144;
            #pragma unroll
            for (int mt = 0; mt < 2; mt++) {
                const int o = mt * 16 + o0;
                const float* c = acc[mt][nt];
                *reinterpret_cast<float*>(rp + o * 4)             = c[0];
                *reinterpret_cast<float*>(rp + 144 + o * 4)       = c[1];
                *reinterpret_cast<float*>(rp + (o + 8) * 4)       = c[2];
                *reinterpret_cast<float*>(rp + 144 + (o + 8) * 4) = c[3];
            }
        }
    }
    __syncwarp();

    // read back (conflict-free) and write 512B-coalesced STG.128
    {
        const int b0 = bg * NSLOT + 2 * w;
        #pragma unroll
        for (int it = 0; it < 18; it++) {
            int q = it * 32 + lane;            // 576 chunks: [s(2)][t(36)][c(8)]
            int s = q / 288;
            int rm = q - s * 288;
            int t = rm >> 3;
            int c = rm & 7;
            float4 v = *reinterpret_cast<const float4*>(stg + s * SSLOT + t * 144 + c * 16);
            float4* op = reinterpret_cast<float4*>(
                out + (((size_t)(b0 + s) * L_ + l) * TOUT + t) * COUT) + c;
            *op = v;
        }
    }
}

extern "C" void kernel_launch(void* const* d_in, const int* in_sizes, int n_in,
                              void* d_out, int out_size)
{
    const float* x    = (const float*)d_in[0];
    const int*   nidx = (const int*)  d_in[1];
    const float* W    = (const float*)d_in[2];
    const float* bias = (const float*)d_in[3];
    float*       out  = (float*)d_out;

    cudaFuncSetAttribute(indexed_conv_hmma,
                         cudaFuncAttributeMaxDynamicSharedMemorySize, SMEM_DYN);

    wfrag_kernel<<<(NF16 + NF8 + 255) / 256, 256>>>(W);
    dim3 grid(L_, B_ / NSLOT);
    indexed_conv_hmma<<<grid, 128, SMEM_DYN>>>(x, nidx, bias, out);
}